// round 1
// baseline (speedup 1.0000x reference)
#include <cuda_runtime.h>
#include <cuda_bf16.h>

#define NN 20000
#define EE 320000
#define CC 256
#define GG 50
#define JKW 768
#define KDIM 512

// ---- scratch (static device globals; no runtime allocation) ----
__device__ int   g_degi[NN];
__device__ int   g_cnt[NN];
__device__ float g_dis[NN];
__device__ int   g_rowptr[NN + 1];
__device__ int   g_ccol[EE];
__device__ float g_cw[EE];
__device__ __align__(16) float g_p[NN * CC];        // prop(h) output
__device__ __align__(16) float g_jk[NN * JKW];      // [h0 | h1 | h2]
__device__ int   g_gstart[GG];
__device__ int   g_gend[GG];

// ---------------------------------------------------------------
__global__ void k_zero() {
    int i = blockIdx.x * blockDim.x + threadIdx.x;
    if (i < NN) { g_degi[i] = 0; g_cnt[i] = 0; }
}

__global__ void k_deg(const int* __restrict__ ei) {
    int e = blockIdx.x * blockDim.x + threadIdx.x;
    if (e < EE) atomicAdd(&g_degi[ei[e]], 1);
}

__global__ void k_dis() {
    int i = blockIdx.x * blockDim.x + threadIdx.x;
    if (i < NN) {
        int d = g_degi[i];
        g_dis[i] = (d > 0) ? rsqrtf((float)d) : 0.0f;
    }
}

// single-block exclusive scan of g_degi -> g_rowptr
__global__ void k_scan() {
    __shared__ int sm[1024];
    int t = threadIdx.x;
    const int CH = (NN + 1023) / 1024;  // 20
    int lo = t * CH;
    int hi = lo + CH; if (hi > NN) hi = NN;
    int s = 0;
    for (int i = lo; i < hi; i++) s += g_degi[i];
    sm[t] = s;
    __syncthreads();
    for (int off = 1; off < 1024; off <<= 1) {
        int v = (t >= off) ? sm[t - off] : 0;
        __syncthreads();
        sm[t] += v;
        __syncthreads();
    }
    int run = (t > 0) ? sm[t - 1] : 0;
    for (int i = lo; i < hi; i++) { g_rowptr[i] = run; run += g_degi[i]; }
    if (t == 1023) g_rowptr[NN] = sm[1023];
}

__global__ void k_fill(const int* __restrict__ ei) {
    int e = blockIdx.x * blockDim.x + threadIdx.x;
    if (e < EE) {
        int r = ei[e];
        int c = ei[e + EE];
        int pos = g_rowptr[r] + atomicAdd(&g_cnt[r], 1);
        g_ccol[pos] = c;
        g_cw[pos]   = -(g_dis[r] * g_dis[c]);
    }
}

// ---------------------------------------------------------------
// SpMM: p[v,:] = sum over in-CSR(v) of w * h_in[col,:]   (one warp per node)
__global__ void k_spmm(const float* __restrict__ x, int layer) {
    int w = (blockIdx.x * blockDim.x + threadIdx.x) >> 5;
    int lane = threadIdx.x & 31;
    if (w >= NN) return;
    const float* hin;
    int ldh;
    if (layer == 0) { hin = x; ldh = CC; }
    else            { hin = g_jk + (size_t)(layer - 1) * CC; ldh = JKW; }

    float4 a0 = {0.f, 0.f, 0.f, 0.f};
    float4 a1 = {0.f, 0.f, 0.f, 0.f};
    int s = g_rowptr[w], e = g_rowptr[w + 1];
    for (int i = s; i < e; i++) {
        int u = g_ccol[i];
        float wt = g_cw[i];
        const float4* src = reinterpret_cast<const float4*>(hin + (size_t)u * ldh);
        float4 v0 = __ldg(&src[lane]);
        float4 v1 = __ldg(&src[lane + 32]);
        a0.x += wt * v0.x; a0.y += wt * v0.y; a0.z += wt * v0.z; a0.w += wt * v0.w;
        a1.x += wt * v1.x; a1.y += wt * v1.y; a1.z += wt * v1.z; a1.w += wt * v1.w;
    }
    float4* dst = reinterpret_cast<float4*>(g_p + (size_t)w * CC);
    dst[lane] = a0;
    dst[lane + 32] = a1;
}

// ---------------------------------------------------------------
// GEMM: out = [h_in | p] @ W (512x256) with fused BN/ReLU epilogue.
// BM=BN=128, BK=16, 256 threads, 8x8 microtile.
__global__ __launch_bounds__(256, 2) void k_gemm(
    const float* __restrict__ x,
    const float* __restrict__ cheb_w,
    const float* __restrict__ gamma,
    const float* __restrict__ beta,
    int layer)
{
    __shared__ float As[16][128];
    __shared__ float Bs[16][128];

    const float* hin;
    int ldh;
    if (layer == 0) { hin = x; ldh = CC; }
    else            { hin = g_jk + (size_t)(layer - 1) * CC; ldh = JKW; }
    const float* W = cheb_w + (size_t)layer * 2 * CC * CC;  // [512][256] row-major

    int m0 = blockIdx.y * 128;
    int n0 = blockIdx.x * 128;
    int tid = threadIdx.x;
    int tx = tid & 15, ty = tid >> 4;

    float acc[8][8];
#pragma unroll
    for (int i = 0; i < 8; i++)
#pragma unroll
        for (int j = 0; j < 8; j++) acc[i][j] = 0.f;

    for (int kt = 0; kt < KDIM / 16; kt++) {
        int kbase = kt * 16;
        const float* abase;
        int alda, acol;
        if (kbase < CC) { abase = hin; alda = ldh; acol = kbase; }
        else            { abase = g_p; alda = CC;  acol = kbase - CC; }

        // load A tile (128 rows x 16 k), transpose into As[k][m]
#pragma unroll
        for (int sgl = 0; sgl < 2; sgl++) {
            int slot = tid + sgl * 256;      // 0..511
            int r  = slot >> 2;              // 0..127
            int k4 = slot & 3;               // 0..3
            int gr = m0 + r;
            float4 v = {0.f, 0.f, 0.f, 0.f};
            if (gr < NN)
                v = *reinterpret_cast<const float4*>(abase + (size_t)gr * alda + acol + k4 * 4);
            As[k4 * 4 + 0][r] = v.x;
            As[k4 * 4 + 1][r] = v.y;
            As[k4 * 4 + 2][r] = v.z;
            As[k4 * 4 + 3][r] = v.w;
        }
        // load B tile (16 k x 128 n)
#pragma unroll
        for (int sgl = 0; sgl < 2; sgl++) {
            int slot = tid + sgl * 256;
            int kr = slot >> 5;              // 0..15
            int j4 = slot & 31;              // 0..31
            float4 v = *reinterpret_cast<const float4*>(W + (size_t)(kbase + kr) * CC + n0 + j4 * 4);
            *reinterpret_cast<float4*>(&Bs[kr][j4 * 4]) = v;
        }
        __syncthreads();

#pragma unroll
        for (int k = 0; k < 16; k++) {
            float ra[8], rb[8];
#pragma unroll
            for (int i = 0; i < 8; i++) ra[i] = As[k][ty * 8 + i];
#pragma unroll
            for (int j = 0; j < 8; j++) rb[j] = Bs[k][tx * 8 + j];
#pragma unroll
            for (int i = 0; i < 8; i++)
#pragma unroll
                for (int j = 0; j < 8; j++)
                    acc[i][j] += ra[i] * rb[j];
        }
        __syncthreads();
    }

    // epilogue: layer 0: relu(bn(v)); layers 1,2: bn(relu(v))
    const float inv = rsqrtf(1.0f + 1e-5f);
#pragma unroll
    for (int i = 0; i < 8; i++) {
        int gr = m0 + ty * 8 + i;
        if (gr < NN) {
#pragma unroll
            for (int j = 0; j < 8; j++) {
                int gc = n0 + tx * 8 + j;
                float s = gamma[layer * CC + gc] * inv;
                float b = beta[layer * CC + gc];
                float v = acc[i][j];
                float o = (layer == 0) ? fmaxf(v * s + b, 0.f)
                                       : (fmaxf(v, 0.f) * s + b);
                g_jk[(size_t)gr * JKW + layer * CC + gc] = o;
            }
        }
    }
}

// ---------------------------------------------------------------
__global__ void k_ranges(const int* __restrict__ batch) {
    int n = blockIdx.x * blockDim.x + threadIdx.x;
    if (n >= NN) return;
    int b = batch[n];
    if (n == 0 || batch[n - 1] != b) g_gstart[b] = n;
    if (n == NN - 1 || batch[n + 1] != b) g_gend[b] = n + 1;
}

__global__ void k_pool(float* __restrict__ out) {
    int g = blockIdx.x;
    int c = blockIdx.y * 128 + threadIdx.x;
    int s = g_gstart[g], e = g_gend[g];
    float acc = 0.f;
    for (int n = s; n < e; n++)
        acc += g_jk[(size_t)n * JKW + c];
    out[g * JKW + c] = acc / (float)(e - s);
}

// classifier: Linear(768->256) -> ReLU -> BN1d(eval) -> Linear(256->2)
__global__ void k_cls(const float* __restrict__ zin,
                      const float* __restrict__ W1, const float* __restrict__ b1,
                      const float* __restrict__ cg, const float* __restrict__ cbe,
                      const float* __restrict__ W2, const float* __restrict__ b2,
                      float* __restrict__ out)
{
    __shared__ float zr[JKW];
    __shared__ float zz[256];
    int g = blockIdx.x, t = threadIdx.x;
    for (int j = t; j < JKW; j += 256) zr[j] = zin[g * JKW + j];
    __syncthreads();

    float acc = b1[t];
    const float* w = W1 + (size_t)t * JKW;
    for (int j = 0; j < JKW; j++) acc += zr[j] * w[j];
    const float inv = rsqrtf(1.0f + 1e-5f);
    zz[t] = fmaxf(acc, 0.f) * cg[t] * inv + cbe[t];
    __syncthreads();

    if (t < 64) {
        int k = t >> 5;        // class 0 / 1
        int lane = t & 31;
        float s = 0.f;
        for (int o = lane; o < 256; o += 32) s += zz[o] * W2[k * 256 + o];
#pragma unroll
        for (int off = 16; off; off >>= 1) s += __shfl_down_sync(0xffffffffu, s, off);
        if (lane == 0) out[GG * JKW + g * 2 + k] = s + b2[k];
    }
}

// ---------------------------------------------------------------
extern "C" void kernel_launch(void* const* d_in, const int* in_sizes, int n_in,
                              void* d_out, int out_size)
{
    const float* x    = (const float*)d_in[0];
    const int*   ei   = (const int*)  d_in[1];
    const int*   batch= (const int*)  d_in[2];
    const float* cw   = (const float*)d_in[3];
    const float* bg   = (const float*)d_in[4];
    const float* bb   = (const float*)d_in[5];
    const float* w1   = (const float*)d_in[6];
    const float* b1   = (const float*)d_in[7];
    const float* cg   = (const float*)d_in[8];
    const float* cbe  = (const float*)d_in[9];
    const float* w2   = (const float*)d_in[10];
    const float* b2   = (const float*)d_in[11];
    float* out = (float*)d_out;

    k_zero<<<(NN + 255) / 256, 256>>>();
    k_deg <<<(EE + 255) / 256, 256>>>(ei);
    k_dis <<<(NN + 255) / 256, 256>>>();
    k_scan<<<1, 1024>>>();
    k_fill<<<(EE + 255) / 256, 256>>>(ei);

    for (int l = 0; l < 3; l++) {
        k_spmm<<<(NN + 7) / 8, 256>>>(x, l);
        dim3 grid(CC / 128, (NN + 127) / 128);
        k_gemm<<<grid, 256>>>(x, cw, bg, bb, l);
    }

    k_ranges<<<(NN + 255) / 256, 256>>>(batch);
    dim3 pg(GG, JKW / 128);
    k_pool<<<pg, 128>>>(out);
    k_cls<<<GG, 256>>>(out, w1, b1, cg, cbe, w2, b2, out);
}

// round 2
// speedup vs baseline: 1.1268x; 1.1268x over previous
#include <cuda_runtime.h>
#include <cuda_bf16.h>
#include <cstdint>

#define NN 20000
#define EE 320000
#define CC 256
#define GG 50
#define JKW 768
#define KDIM 512

// ---- scratch (static device globals; no runtime allocation) ----
__device__ int   g_degi[NN];
__device__ int   g_cnt[NN];
__device__ float g_dis[NN];
__device__ int   g_rowptr[NN + 1];
__device__ int   g_ccol[EE];
__device__ float g_cw[EE];
__device__ __align__(16) float g_p[NN * CC];        // prop(h) output
__device__ __align__(16) float g_jk[NN * JKW];      // [h0 | h1 | h2]
__device__ int   g_gstart[GG];
__device__ int   g_gend[GG];

// ---------------------------------------------------------------
__global__ void k_zero() {
    int i = blockIdx.x * blockDim.x + threadIdx.x;
    if (i < NN) { g_degi[i] = 0; g_cnt[i] = 0; }
}

__global__ void k_deg(const int* __restrict__ ei) {
    int e = blockIdx.x * blockDim.x + threadIdx.x;
    if (e < EE) atomicAdd(&g_degi[ei[e]], 1);
}

__global__ void k_dis() {
    int i = blockIdx.x * blockDim.x + threadIdx.x;
    if (i < NN) {
        int d = g_degi[i];
        g_dis[i] = (d > 0) ? rsqrtf((float)d) : 0.0f;
    }
}

// single-block exclusive scan of g_degi -> g_rowptr
__global__ void k_scan() {
    __shared__ int sm[1024];
    int t = threadIdx.x;
    const int CH = (NN + 1023) / 1024;  // 20
    int lo = t * CH;
    int hi = lo + CH; if (hi > NN) hi = NN;
    int s = 0;
    for (int i = lo; i < hi; i++) s += g_degi[i];
    sm[t] = s;
    __syncthreads();
    for (int off = 1; off < 1024; off <<= 1) {
        int v = (t >= off) ? sm[t - off] : 0;
        __syncthreads();
        sm[t] += v;
        __syncthreads();
    }
    int run = (t > 0) ? sm[t - 1] : 0;
    for (int i = lo; i < hi; i++) { g_rowptr[i] = run; run += g_degi[i]; }
    if (t == 1023) g_rowptr[NN] = sm[1023];
}

__global__ void k_fill(const int* __restrict__ ei) {
    int e = blockIdx.x * blockDim.x + threadIdx.x;
    if (e < EE) {
        int r = ei[e];
        int c = ei[e + EE];
        int pos = g_rowptr[r] + atomicAdd(&g_cnt[r], 1);
        g_ccol[pos] = c;
        g_cw[pos]   = -(g_dis[r] * g_dis[c]);
    }
}

// ---------------------------------------------------------------
// SpMM: p[v,:] = sum over in-CSR(v) of w * h_in[col,:]   (one warp per node)
__global__ void k_spmm(const float* __restrict__ x, int layer) {
    int w = (blockIdx.x * blockDim.x + threadIdx.x) >> 5;
    int lane = threadIdx.x & 31;
    if (w >= NN) return;
    const float* hin;
    int ldh;
    if (layer == 0) { hin = x; ldh = CC; }
    else            { hin = g_jk + (size_t)(layer - 1) * CC; ldh = JKW; }

    float4 a0 = {0.f, 0.f, 0.f, 0.f};
    float4 a1 = {0.f, 0.f, 0.f, 0.f};
    int s = g_rowptr[w], e = g_rowptr[w + 1];
    for (int i = s; i < e; i++) {
        int u = g_ccol[i];
        float wt = g_cw[i];
        const float4* src = reinterpret_cast<const float4*>(hin + (size_t)u * ldh);
        float4 v0 = __ldg(&src[lane]);
        float4 v1 = __ldg(&src[lane + 32]);
        a0.x += wt * v0.x; a0.y += wt * v0.y; a0.z += wt * v0.z; a0.w += wt * v0.w;
        a1.x += wt * v1.x; a1.y += wt * v1.y; a1.z += wt * v1.z; a1.w += wt * v1.w;
    }
    float4* dst = reinterpret_cast<float4*>(g_p + (size_t)w * CC);
    dst[lane] = a0;
    dst[lane + 32] = a1;
}

// ---------------------------------------------------------------
// tf32 helpers
__device__ __forceinline__ float to_tf32(float v) {
    uint32_t b;
    asm("cvt.rna.tf32.f32 %0, %1;" : "=r"(b) : "f"(v));
    return __uint_as_float(b);
}

__device__ __forceinline__ void mma_tf32(float& d0, float& d1, float& d2, float& d3,
                                         float a0, float a1, float a2, float a3,
                                         float b0, float b1) {
    asm volatile(
        "mma.sync.aligned.m16n8k8.row.col.f32.tf32.tf32.f32 "
        "{%0,%1,%2,%3}, {%4,%5,%6,%7}, {%8,%9}, {%0,%1,%2,%3};"
        : "+f"(d0), "+f"(d1), "+f"(d2), "+f"(d3)
        : "r"(__float_as_uint(a0)), "r"(__float_as_uint(a1)),
          "r"(__float_as_uint(a2)), "r"(__float_as_uint(a3)),
          "r"(__float_as_uint(b0)), "r"(__float_as_uint(b1)));
}

// ---------------------------------------------------------------
// Tensor-core GEMM (tf32x3): out = [h_in | p] @ W (512x256), fused BN/ReLU.
// Block 128(M) x 128(N), 8 warps (2x4), warp tile 64x32, k-tile 16.
__global__ __launch_bounds__(256, 2) void k_gemm_tc(
    const float* __restrict__ x,
    const float* __restrict__ cheb_w,
    const float* __restrict__ gamma,
    const float* __restrict__ beta,
    int layer)
{
    __shared__ float Abig[16][132];
    __shared__ float Asml[16][132];
    __shared__ float Bbig[16][132];
    __shared__ float Bsml[16][132];

    const float* hin;
    int ldh;
    if (layer == 0) { hin = x; ldh = CC; }
    else            { hin = g_jk + (size_t)(layer - 1) * CC; ldh = JKW; }
    const float* W = cheb_w + (size_t)layer * 2 * CC * CC;  // [512][256] row-major

    const int m0 = blockIdx.y * 128;
    const int n0 = blockIdx.x * 128;
    const int tid  = threadIdx.x;
    const int warp = tid >> 5;
    const int lane = tid & 31;
    const int wm = warp >> 2;            // 0..1
    const int wn = warp & 3;             // 0..3
    const int m0w = wm * 64;
    const int n0w = wn * 32;
    const int gid = lane >> 2;           // groupID 0..7
    const int tig = lane & 3;            // threadID_in_group 0..3

    float acc[4][4][4];
#pragma unroll
    for (int mi = 0; mi < 4; mi++)
#pragma unroll
        for (int ni = 0; ni < 4; ni++)
#pragma unroll
            for (int r = 0; r < 4; r++) acc[mi][ni][r] = 0.f;

    for (int kt = 0; kt < KDIM / 16; kt++) {
        const int kbase = kt * 16;
        const float* abase;
        int alda, acol;
        if (kbase < CC) { abase = hin; alda = ldh; acol = kbase; }
        else            { abase = g_p; alda = CC;  acol = kbase - CC; }

        // ---- load A tile (128 rows x 16 k) with tf32 big/small split ----
#pragma unroll
        for (int sgl = 0; sgl < 2; sgl++) {
            int slot = tid + sgl * 256;      // 0..511
            int r  = slot >> 2;              // 0..127
            int k4 = slot & 3;               // 0..3
            int gr = m0 + r;
            float4 v = {0.f, 0.f, 0.f, 0.f};
            if (gr < NN)
                v = *reinterpret_cast<const float4*>(abase + (size_t)gr * alda + acol + k4 * 4);
            float vv[4] = {v.x, v.y, v.z, v.w};
#pragma unroll
            for (int c = 0; c < 4; c++) {
                float bg = to_tf32(vv[c]);
                Abig[k4 * 4 + c][r] = bg;
                Asml[k4 * 4 + c][r] = to_tf32(vv[c] - bg);
            }
        }
        // ---- load B tile (16 k x 128 n) with split ----
#pragma unroll
        for (int sgl = 0; sgl < 2; sgl++) {
            int slot = tid + sgl * 256;
            int kr = slot >> 5;              // 0..15
            int j4 = slot & 31;              // 0..31
            float4 v = *reinterpret_cast<const float4*>(W + (size_t)(kbase + kr) * CC + n0 + j4 * 4);
            float vv[4] = {v.x, v.y, v.z, v.w};
#pragma unroll
            for (int c = 0; c < 4; c++) {
                float bg = to_tf32(vv[c]);
                Bbig[kr][j4 * 4 + c] = bg;
                Bsml[kr][j4 * 4 + c] = to_tf32(vv[c] - bg);
            }
        }
        __syncthreads();

#pragma unroll
        for (int ks = 0; ks < 2; ks++) {
            const int kb = ks * 8;
            // B fragments (persistent across mi)
            float bb[4][2], bs[4][2];
#pragma unroll
            for (int ni = 0; ni < 4; ni++) {
                int n_ = n0w + ni * 8 + gid;
                bb[ni][0] = Bbig[kb + tig][n_];
                bb[ni][1] = Bbig[kb + tig + 4][n_];
                bs[ni][0] = Bsml[kb + tig][n_];
                bs[ni][1] = Bsml[kb + tig + 4][n_];
            }
#pragma unroll
            for (int mi = 0; mi < 4; mi++) {
                int m_ = m0w + mi * 16 + gid;
                float ab0 = Abig[kb + tig][m_];
                float ab1 = Abig[kb + tig][m_ + 8];
                float ab2 = Abig[kb + tig + 4][m_];
                float ab3 = Abig[kb + tig + 4][m_ + 8];
                float as0 = Asml[kb + tig][m_];
                float as1 = Asml[kb + tig][m_ + 8];
                float as2 = Asml[kb + tig + 4][m_];
                float as3 = Asml[kb + tig + 4][m_ + 8];
#pragma unroll
                for (int ni = 0; ni < 4; ni++) {
                    mma_tf32(acc[mi][ni][0], acc[mi][ni][1], acc[mi][ni][2], acc[mi][ni][3],
                             ab0, ab1, ab2, ab3, bb[ni][0], bb[ni][1]);
                    mma_tf32(acc[mi][ni][0], acc[mi][ni][1], acc[mi][ni][2], acc[mi][ni][3],
                             as0, as1, as2, as3, bb[ni][0], bb[ni][1]);
                    mma_tf32(acc[mi][ni][0], acc[mi][ni][1], acc[mi][ni][2], acc[mi][ni][3],
                             ab0, ab1, ab2, ab3, bs[ni][0], bs[ni][1]);
                }
            }
        }
        __syncthreads();
    }

    // epilogue: layer 0: relu(bn(v)); layers 1,2: bn(relu(v))
    const float inv = rsqrtf(1.0f + 1e-5f);
#pragma unroll
    for (int mi = 0; mi < 4; mi++) {
        int gr0 = m0 + m0w + mi * 16 + gid;
        int gr1 = gr0 + 8;
#pragma unroll
        for (int ni = 0; ni < 4; ni++) {
            int gc = n0 + n0w + ni * 8 + 2 * tig;
            float s0 = gamma[layer * CC + gc]     * inv;
            float s1 = gamma[layer * CC + gc + 1] * inv;
            float b0 = beta[layer * CC + gc];
            float b1 = beta[layer * CC + gc + 1];
            float v0 = acc[mi][ni][0], v1 = acc[mi][ni][1];
            float v2 = acc[mi][ni][2], v3 = acc[mi][ni][3];
            float o0, o1, o2, o3;
            if (layer == 0) {
                o0 = fmaxf(v0 * s0 + b0, 0.f); o1 = fmaxf(v1 * s1 + b1, 0.f);
                o2 = fmaxf(v2 * s0 + b0, 0.f); o3 = fmaxf(v3 * s1 + b1, 0.f);
            } else {
                o0 = fmaxf(v0, 0.f) * s0 + b0; o1 = fmaxf(v1, 0.f) * s1 + b1;
                o2 = fmaxf(v2, 0.f) * s0 + b0; o3 = fmaxf(v3, 0.f) * s1 + b1;
            }
            if (gr0 < NN)
                *reinterpret_cast<float2*>(&g_jk[(size_t)gr0 * JKW + layer * CC + gc]) = make_float2(o0, o1);
            if (gr1 < NN)
                *reinterpret_cast<float2*>(&g_jk[(size_t)gr1 * JKW + layer * CC + gc]) = make_float2(o2, o3);
        }
    }
}

// ---------------------------------------------------------------
__global__ void k_ranges(const int* __restrict__ batch) {
    int n = blockIdx.x * blockDim.x + threadIdx.x;
    if (n >= NN) return;
    int b = batch[n];
    if (n == 0 || batch[n - 1] != b) g_gstart[b] = n;
    if (n == NN - 1 || batch[n + 1] != b) g_gend[b] = n + 1;
}

__global__ void k_pool(float* __restrict__ out) {
    int g = blockIdx.x;
    int c = blockIdx.y * 128 + threadIdx.x;
    int s = g_gstart[g], e = g_gend[g];
    float acc = 0.f;
    for (int n = s; n < e; n++)
        acc += g_jk[(size_t)n * JKW + c];
    out[g * JKW + c] = acc / (float)(e - s);
}

// classifier: Linear(768->256) -> ReLU -> BN1d(eval) -> Linear(256->2)
__global__ void k_cls(const float* __restrict__ zin,
                      const float* __restrict__ W1, const float* __restrict__ b1,
                      const float* __restrict__ cg, const float* __restrict__ cbe,
                      const float* __restrict__ W2, const float* __restrict__ b2,
                      float* __restrict__ out)
{
    __shared__ float zr[JKW];
    __shared__ float zz[256];
    int g = blockIdx.x, t = threadIdx.x;
    for (int j = t; j < JKW; j += 256) zr[j] = zin[g * JKW + j];
    __syncthreads();

    float acc = b1[t];
    const float* w = W1 + (size_t)t * JKW;
    for (int j = 0; j < JKW; j++) acc += zr[j] * w[j];
    const float inv = rsqrtf(1.0f + 1e-5f);
    zz[t] = fmaxf(acc, 0.f) * cg[t] * inv + cbe[t];
    __syncthreads();

    if (t < 64) {
        int k = t >> 5;        // class 0 / 1
        int lane = t & 31;
        float s = 0.f;
        for (int o = lane; o < 256; o += 32) s += zz[o] * W2[k * 256 + o];
#pragma unroll
        for (int off = 16; off; off >>= 1) s += __shfl_down_sync(0xffffffffu, s, off);
        if (lane == 0) out[GG * JKW + g * 2 + k] = s + b2[k];
    }
}

// ---------------------------------------------------------------
extern "C" void kernel_launch(void* const* d_in, const int* in_sizes, int n_in,
                              void* d_out, int out_size)
{
    const float* x    = (const float*)d_in[0];
    const int*   ei   = (const int*)  d_in[1];
    const int*   batch= (const int*)  d_in[2];
    const float* cw   = (const float*)d_in[3];
    const float* bg   = (const float*)d_in[4];
    const float* bb   = (const float*)d_in[5];
    const float* w1   = (const float*)d_in[6];
    const float* b1   = (const float*)d_in[7];
    const float* cg   = (const float*)d_in[8];
    const float* cbe  = (const float*)d_in[9];
    const float* w2   = (const float*)d_in[10];
    const float* b2   = (const float*)d_in[11];
    float* out = (float*)d_out;

    k_zero<<<(NN + 255) / 256, 256>>>();
    k_deg <<<(EE + 255) / 256, 256>>>(ei);
    k_dis <<<(NN + 255) / 256, 256>>>();
    k_scan<<<1, 1024>>>();
    k_fill<<<(EE + 255) / 256, 256>>>(ei);

    for (int l = 0; l < 3; l++) {
        k_spmm<<<(NN + 7) / 8, 256>>>(x, l);
        dim3 grid(CC / 128, (NN + 127) / 128);
        k_gemm_tc<<<grid, 256>>>(x, cw, bg, bb, l);
    }

    k_ranges<<<(NN + 255) / 256, 256>>>(batch);
    dim3 pg(GG, JKW / 128);
    k_pool<<<pg, 128>>>(out);
    k_cls<<<GG, 256>>>(out, w1, b1, cg, cbe, w2, b2, out);
}

// round 4
// speedup vs baseline: 1.6275x; 1.4444x over previous
#include <cuda_runtime.h>
#include <cuda_fp16.h>
#include <cstdint>

#define NN 20000
#define EE 320000
#define CC 256
#define GG 50
#define JKW 768
#define KDIM 512
#define HSZ (NN * CC)

#define STG_BYTES 40960          // A big 10240 | A sml 10240 | B big 10240 | B sml 10240
#define SMEM_TOT (2 * STG_BYTES) // 80 KB, double buffered

// ---- scratch (static device globals; no runtime allocation) ----
__device__ int   g_degi[NN];
__device__ int   g_cnt[NN];
__device__ float g_dis[NN];
__device__ int   g_rowptr[NN + 1];
__device__ int   g_ccol[EE];
__device__ float g_cw[EE];
__device__ __align__(16) float  g_jk[NN * JKW];     // [h0 | h1 | h2] fp32 (for pool + spmm)
__device__ __align__(16) __half g_hb[2 * HSZ];      // h big,  ping-pong by layer
__device__ __align__(16) __half g_hs[2 * HSZ];      // h small (unscaled residual)
__device__ __align__(16) __half g_pb[HSZ];          // p big
__device__ __align__(16) __half g_ps[HSZ];          // p small
__device__ __align__(16) __half g_wb[3 * CC * KDIM];// W^T big  [l][n][k]
__device__ __align__(16) __half g_ws[3 * CC * KDIM];// W^T small
__device__ int   g_gstart[GG];
__device__ int   g_gend[GG];

// ---------------- helpers ----------------
__device__ __forceinline__ uint32_t smem_u32(const void* p) {
    uint32_t a;
    asm("{ .reg .u64 t; cvta.to.shared.u64 t, %1; cvt.u32.u64 %0, t; }" : "=r"(a) : "l"(p));
    return a;
}

__device__ __forceinline__ void cpa16(uint32_t dst, const void* src, int sz) {
    asm volatile("cp.async.ca.shared.global [%0], [%1], 16, %2;\n"
                 :: "r"(dst), "l"(src), "r"(sz));
}

__device__ __forceinline__ void mma_f16(float& d0, float& d1, float& d2, float& d3,
                                        uint32_t a0, uint32_t a1, uint32_t a2, uint32_t a3,
                                        uint32_t b0, uint32_t b1) {
    asm volatile(
        "mma.sync.aligned.m16n8k16.row.col.f32.f16.f16.f32 "
        "{%0,%1,%2,%3}, {%4,%5,%6,%7}, {%8,%9}, {%0,%1,%2,%3};"
        : "+f"(d0), "+f"(d1), "+f"(d2), "+f"(d3)
        : "r"(a0), "r"(a1), "r"(a2), "r"(a3), "r"(b0), "r"(b1));
}

// ---------------------------------------------------------------
__global__ void k_zero() {
    int i = blockIdx.x * blockDim.x + threadIdx.x;
    if (i < NN) { g_degi[i] = 0; g_cnt[i] = 0; }
}

__global__ void k_deg(const int* __restrict__ ei) {
    int e = blockIdx.x * blockDim.x + threadIdx.x;
    if (e < EE) atomicAdd(&g_degi[ei[e]], 1);
}

__global__ void k_dis() {
    int i = blockIdx.x * blockDim.x + threadIdx.x;
    if (i < NN) {
        int d = g_degi[i];
        g_dis[i] = (d > 0) ? rsqrtf((float)d) : 0.0f;
    }
}

__global__ void k_scan() {
    __shared__ int sm[1024];
    int t = threadIdx.x;
    const int CH = (NN + 1023) / 1024;
    int lo = t * CH;
    int hi = lo + CH; if (hi > NN) hi = NN;
    int s = 0;
    for (int i = lo; i < hi; i++) s += g_degi[i];
    sm[t] = s;
    __syncthreads();
    for (int off = 1; off < 1024; off <<= 1) {
        int v = (t >= off) ? sm[t - off] : 0;
        __syncthreads();
        sm[t] += v;
        __syncthreads();
    }
    int run = (t > 0) ? sm[t - 1] : 0;
    for (int i = lo; i < hi; i++) { g_rowptr[i] = run; run += g_degi[i]; }
    if (t == 1023) g_rowptr[NN] = sm[1023];
}

__global__ void k_fill(const int* __restrict__ ei) {
    int e = blockIdx.x * blockDim.x + threadIdx.x;
    if (e < EE) {
        int r = ei[e];
        int c = ei[e + EE];
        int pos = g_rowptr[r] + atomicAdd(&g_cnt[r], 1);
        g_ccol[pos] = c;
        g_cw[pos]   = -(g_dis[r] * g_dis[c]);
    }
}

// ---------------------------------------------------------------
// split helpers: v -> fp16 big + fp16 small (unscaled residual)
__device__ __forceinline__ void split2(float v, __half& b, __half& s) {
    b = __float2half_rn(v);
    s = __float2half_rn(v - __half2float(b));
}

// x (layer-0 h) split into ping buffer 0
__global__ void k_xsplit(const float* __restrict__ x) {
    int i = blockIdx.x * blockDim.x + threadIdx.x;
    if (i >= HSZ) return;
    __half b, s;
    split2(x[i], b, s);
    g_hb[i] = b;
    g_hs[i] = s;
}

// W split: cheb_w[l][k][n] fp32 -> [l][n][k] fp16 big/small
__global__ void k_wsplit(const float* __restrict__ cw) {
    int i = blockIdx.x * blockDim.x + threadIdx.x;
    if (i >= 3 * KDIM * CC) return;
    int n = i & 255;
    int k = (i >> 8) & 511;
    int l = i >> 17;
    __half b, s;
    split2(cw[((size_t)l * KDIM + k) * CC + n], b, s);
    g_wb[((size_t)l * CC + n) * KDIM + k] = b;
    g_ws[((size_t)l * CC + n) * KDIM + k] = s;
}

// ---------------------------------------------------------------
// SpMM: p[v,:] = sum_{CSR(v)} w * h_in[col,:]; outputs fp16 big/small split.
__global__ void k_spmm(const float* __restrict__ x, int layer) {
    int w = (blockIdx.x * blockDim.x + threadIdx.x) >> 5;
    int lane = threadIdx.x & 31;
    if (w >= NN) return;
    const float* hin;
    int ldh;
    if (layer == 0) { hin = x; ldh = CC; }
    else            { hin = g_jk + (size_t)(layer - 1) * CC; ldh = JKW; }

    float4 a0 = {0.f, 0.f, 0.f, 0.f};
    float4 a1 = {0.f, 0.f, 0.f, 0.f};
    int s = g_rowptr[w], e = g_rowptr[w + 1];
    for (int i = s; i < e; i++) {
        int u = g_ccol[i];
        float wt = g_cw[i];
        const float4* src = reinterpret_cast<const float4*>(hin + (size_t)u * ldh);
        float4 v0 = __ldg(&src[lane]);
        float4 v1 = __ldg(&src[lane + 32]);
        a0.x += wt * v0.x; a0.y += wt * v0.y; a0.z += wt * v0.z; a0.w += wt * v0.w;
        a1.x += wt * v1.x; a1.y += wt * v1.y; a1.z += wt * v1.z; a1.w += wt * v1.w;
    }
    // split + store (cols lane*4 and 128+lane*4)
    __half2 pb0, pb1, ps0, ps1;
    {
        __half b0, b1, s0, s1;
        split2(a0.x, b0, s0); split2(a0.y, b1, s1);
        pb0 = __halves2half2(b0, b1); ps0 = __halves2half2(s0, s1);
        split2(a0.z, b0, s0); split2(a0.w, b1, s1);
        pb1 = __halves2half2(b0, b1); ps1 = __halves2half2(s0, s1);
    }
    size_t o0 = (size_t)w * CC + lane * 4;
    *reinterpret_cast<__half2*>(&g_pb[o0])     = pb0;
    *reinterpret_cast<__half2*>(&g_pb[o0 + 2]) = pb1;
    *reinterpret_cast<__half2*>(&g_ps[o0])     = ps0;
    *reinterpret_cast<__half2*>(&g_ps[o0 + 2]) = ps1;
    {
        __half b0, b1, s0, s1;
        split2(a1.x, b0, s0); split2(a1.y, b1, s1);
        pb0 = __halves2half2(b0, b1); ps0 = __halves2half2(s0, s1);
        split2(a1.z, b0, s0); split2(a1.w, b1, s1);
        pb1 = __halves2half2(b0, b1); ps1 = __halves2half2(s0, s1);
    }
    size_t o1 = (size_t)w * CC + 128 + lane * 4;
    *reinterpret_cast<__half2*>(&g_pb[o1])     = pb0;
    *reinterpret_cast<__half2*>(&g_pb[o1 + 2]) = pb1;
    *reinterpret_cast<__half2*>(&g_ps[o1])     = ps0;
    *reinterpret_cast<__half2*>(&g_ps[o1 + 2]) = ps1;
}

// ---------------------------------------------------------------
// Tile loader: A 128x32 (fp16 big+sml) + B 128x32 (fp16 big+sml), rows padded to 40 halves.
__device__ __forceinline__ void issue_tile(
    uint32_t sb, int stage, int kt, int m0, int n0,
    const __half* __restrict__ hb, const __half* __restrict__ hs,
    const __half* __restrict__ wb, const __half* __restrict__ ws, int tid)
{
    uint32_t base = sb + stage * STG_BYTES;
    int kbase = kt * 32;
    const __half* ab; const __half* asml; int acol;
    if (kbase < CC) { ab = hb;   asml = hs;   acol = kbase; }
    else            { ab = g_pb; asml = g_ps; acol = kbase - CC; }
#pragma unroll
    for (int rep = 0; rep < 4; rep++) {
        int idx = tid + rep * 256;       // 0..1023
        int arr = idx >> 9;              // 0 big, 1 small
        int r   = (idx >> 2) & 127;
        int ch  = idx & 3;
        const __half* s0 = arr ? asml : ab;
        int gr = m0 + r;
        int sz = (gr < NN) ? 16 : 0;
        if (gr >= NN) gr = NN - 1;
        cpa16(base + arr * 10240 + r * 80 + ch * 16,
              s0 + (size_t)gr * CC + acol + ch * 8, sz);
    }
#pragma unroll
    for (int rep = 0; rep < 4; rep++) {
        int idx = tid + rep * 256;
        int arr = idx >> 9;
        int r   = (idx >> 2) & 127;
        int ch  = idx & 3;
        const __half* s0 = arr ? ws : wb;
        cpa16(base + 20480 + arr * 10240 + r * 80 + ch * 16,
              s0 + (size_t)(n0 + r) * KDIM + kbase + ch * 8, 16);
    }
}

// ---------------------------------------------------------------
// fp16x3 GEMM: g_jk[:, l*256 + n0..] = BN/ReLU([h|p] @ W), also writes next-layer h split.
// Block 128M x 128N, 8 warps (2m x 4n), warp tile 64x32, ktile 32, double-buffered cp.async.
__global__ __launch_bounds__(256, 2) void k_gemm(
    const float* __restrict__ gamma,
    const float* __restrict__ beta,
    int layer)
{
    extern __shared__ char smc[];
    uint32_t sb = smem_u32(smc);
    const int tid = threadIdx.x;
    const int wid = tid >> 5, lane = tid & 31;
    const int wm = wid >> 2, wn = wid & 3;
    const int gid = lane >> 2, tig = lane & 3;
    const int m0 = blockIdx.x * 128;
    const int n0 = blockIdx.y * 128;

    const __half* hb = g_hb + (size_t)(layer & 1) * HSZ;
    const __half* hs = g_hs + (size_t)(layer & 1) * HSZ;
    const __half* wb = g_wb + (size_t)layer * CC * KDIM;
    const __half* ws = g_ws + (size_t)layer * CC * KDIM;

    float acc[4][4][4];
#pragma unroll
    for (int mi = 0; mi < 4; mi++)
#pragma unroll
        for (int ni = 0; ni < 4; ni++)
#pragma unroll
            for (int r = 0; r < 4; r++) acc[mi][ni][r] = 0.f;

    issue_tile(sb, 0, 0, m0, n0, hb, hs, wb, ws, tid);
    asm volatile("cp.async.commit_group;");

    for (int kt = 0; kt < 16; kt++) {
        if (kt < 15) {
            issue_tile(sb, (kt + 1) & 1, kt + 1, m0, n0, hb, hs, wb, ws, tid);
            asm volatile("cp.async.commit_group;");
            asm volatile("cp.async.wait_group 1;");
        } else {
            asm volatile("cp.async.wait_group 0;");
        }
        __syncthreads();

        const int stg = (kt & 1) * STG_BYTES;
#pragma unroll
        for (int ks = 0; ks < 2; ks++) {
            const int kk = ks * 16;
            uint32_t bb[4][2], bsm[4][2];
#pragma unroll
            for (int ni = 0; ni < 4; ni++) {
                int boff = stg + 20480 + (wn * 32 + ni * 8 + gid) * 80 + (kk + 2 * tig) * 2;
                bb[ni][0]  = *reinterpret_cast<const uint32_t*>(smc + boff);
                bb[ni][1]  = *reinterpret_cast<const uint32_t*>(smc + boff + 16);
                bsm[ni][0] = *reinterpret_cast<const uint32_t*>(smc + boff + 10240);
                bsm[ni][1] = *reinterpret_cast<const uint32_t*>(smc + boff + 10240 + 16);
            }
#pragma unroll
            for (int mi = 0; mi < 4; mi++) {
                int aoff = stg + (wm * 64 + mi * 16 + gid) * 80 + (kk + 2 * tig) * 2;
                uint32_t ab0 = *reinterpret_cast<const uint32_t*>(smc + aoff);
                uint32_t ab1 = *reinterpret_cast<const uint32_t*>(smc + aoff + 640);
                uint32_t ab2 = *reinterpret_cast<const uint32_t*>(smc + aoff + 16);
                uint32_t ab3 = *reinterpret_cast<const uint32_t*>(smc + aoff + 656);
                uint32_t as0 = *reinterpret_cast<const uint32_t*>(smc + aoff + 10240);
                uint32_t as1 = *reinterpret_cast<const uint32_t*>(smc + aoff + 10240 + 640);
                uint32_t as2 = *reinterpret_cast<const uint32_t*>(smc + aoff + 10240 + 16);
                uint32_t as3 = *reinterpret_cast<const uint32_t*>(smc + aoff + 10240 + 656);
#pragma unroll
                for (int ni = 0; ni < 4; ni++) {
                    mma_f16(acc[mi][ni][0], acc[mi][ni][1], acc[mi][ni][2], acc[mi][ni][3],
                            ab0, ab1, ab2, ab3, bb[ni][0], bb[ni][1]);
                    mma_f16(acc[mi][ni][0], acc[mi][ni][1], acc[mi][ni][2], acc[mi][ni][3],
                            as0, as1, as2, as3, bb[ni][0], bb[ni][1]);
                    mma_f16(acc[mi][ni][0], acc[mi][ni][1], acc[mi][ni][2], acc[mi][ni][3],
                            ab0, ab1, ab2, ab3, bsm[ni][0], bsm[ni][1]);
                }
            }
        }
        __syncthreads();
    }

    // epilogue: BN/ReLU, write g_jk fp32 + next-layer h split (layers 0,1)
    const float inv = rsqrtf(1.0f + 1e-5f);
    __half* ob = g_hb + (size_t)((layer + 1) & 1) * HSZ;
    __half* os = g_hs + (size_t)((layer + 1) & 1) * HSZ;
    const bool wr_split = (layer < 2);
#pragma unroll
    for (int ni = 0; ni < 4; ni++) {
        int c = n0 + wn * 32 + ni * 8 + 2 * tig;
        float s0 = __ldg(&gamma[layer * CC + c])     * inv;
        float s1 = __ldg(&gamma[layer * CC + c + 1]) * inv;
        float b0 = __ldg(&beta[layer * CC + c]);
        float b1 = __ldg(&beta[layer * CC + c + 1]);
#pragma unroll
        for (int mi = 0; mi < 4; mi++) {
            int r0 = m0 + wm * 64 + mi * 16 + gid;
            int r1 = r0 + 8;
            float v0 = acc[mi][ni][0], v1 = acc[mi][ni][1];
            float v2 = acc[mi][ni][2], v3 = acc[mi][ni][3];
            float o0, o1, o2, o3;
            if (layer == 0) {
                o0 = fmaxf(v0 * s0 + b0, 0.f); o1 = fmaxf(v1 * s1 + b1, 0.f);
                o2 = fmaxf(v2 * s0 + b0, 0.f); o3 = fmaxf(v3 * s1 + b1, 0.f);
            } else {
                o0 = fmaxf(v0, 0.f) * s0 + b0; o1 = fmaxf(v1, 0.f) * s1 + b1;
                o2 = fmaxf(v2, 0.f) * s0 + b0; o3 = fmaxf(v3, 0.f) * s1 + b1;
            }
            if (r0 < NN) {
                *reinterpret_cast<float2*>(&g_jk[(size_t)r0 * JKW + layer * CC + c]) = make_float2(o0, o1);
                if (wr_split) {
                    __half hb0, hs0, hb1, hs1;
                    split2(o0, hb0, hs0); split2(o1, hb1, hs1);
                    *reinterpret_cast<__half2*>(&ob[(size_t)r0 * CC + c]) = __halves2half2(hb0, hb1);
                    *reinterpret_cast<__half2*>(&os[(size_t)r0 * CC + c]) = __halves2half2(hs0, hs1);
                }
            }
            if (r1 < NN) {
                *reinterpret_cast<float2*>(&g_jk[(size_t)r1 * JKW + layer * CC + c]) = make_float2(o2, o3);
                if (wr_split) {
                    __half hb0, hs0, hb1, hs1;
                    split2(o2, hb0, hs0); split2(o3, hb1, hs1);
                    *reinterpret_cast<__half2*>(&ob[(size_t)r1 * CC + c]) = __halves2half2(hb0, hb1);
                    *reinterpret_cast<__half2*>(&os[(size_t)r1 * CC + c]) = __halves2half2(hs0, hs1);
                }
            }
        }
    }
}

// ---------------------------------------------------------------
__global__ void k_ranges(const int* __restrict__ batch) {
    int n = blockIdx.x * blockDim.x + threadIdx.x;
    if (n >= NN) return;
    int b = batch[n];
    if (n == 0 || batch[n - 1] != b) g_gstart[b] = n;
    if (n == NN - 1 || batch[n + 1] != b) g_gend[b] = n + 1;
}

__global__ void k_pool(float* __restrict__ out) {
    int g = blockIdx.x;
    int c = blockIdx.y * 128 + threadIdx.x;
    int s = g_gstart[g], e = g_gend[g];
    float acc = 0.f;
    for (int n = s; n < e; n++)
        acc += g_jk[(size_t)n * JKW + c];
    out[g * JKW + c] = acc / (float)(e - s);
}

__global__ void k_cls(const float* __restrict__ zin,
                      const float* __restrict__ W1, const float* __restrict__ b1,
                      const float* __restrict__ cg, const float* __restrict__ cbe,
                      const float* __restrict__ W2, const float* __restrict__ b2,
                      float* __restrict__ out)
{
    __shared__ float zr[JKW];
    __shared__ float zz[256];
    int g = blockIdx.x, t = threadIdx.x;
    for (int j = t; j < JKW; j += 256) zr[j] = zin[g * JKW + j];
    __syncthreads();

    float acc = b1[t];
    const float* w = W1 + (size_t)t * JKW;
    for (int j = 0; j < JKW; j++) acc += zr[j] * w[j];
    const float inv = rsqrtf(1.0f + 1e-5f);
    zz[t] = fmaxf(acc, 0.f) * cg[t] * inv + cbe[t];
    __syncthreads();

    if (t < 64) {
        int k = t >> 5;
        int lane = t & 31;
        float s = 0.f;
        for (int o = lane; o < 256; o += 32) s += zz[o] * W2[k * 256 + o];
#pragma unroll
        for (int off = 16; off; off >>= 1) s += __shfl_down_sync(0xffffffffu, s, off);
        if (lane == 0) out[GG * JKW + g * 2 + k] = s + b2[k];
    }
}

// ---------------------------------------------------------------
extern "C" void kernel_launch(void* const* d_in, const int* in_sizes, int n_in,
                              void* d_out, int out_size)
{
    const float* x    = (const float*)d_in[0];
    const int*   ei   = (const int*)  d_in[1];
    const int*   batch= (const int*)  d_in[2];
    const float* cw   = (const float*)d_in[3];
    const float* bg   = (const float*)d_in[4];
    const float* bb   = (const float*)d_in[5];
    const float* w1   = (const float*)d_in[6];
    const float* b1   = (const float*)d_in[7];
    const float* cg   = (const float*)d_in[8];
    const float* cbe  = (const float*)d_in[9];
    const float* w2   = (const float*)d_in[10];
    const float* b2   = (const float*)d_in[11];
    float* out = (float*)d_out;

    cudaFuncSetAttribute(k_gemm, cudaFuncAttributeMaxDynamicSharedMemorySize, SMEM_TOT);

    k_zero<<<(NN + 255) / 256, 256>>>();
    k_deg <<<(EE + 255) / 256, 256>>>(ei);
    k_dis <<<(NN + 255) / 256, 256>>>();
    k_scan<<<1, 1024>>>();
    k_fill<<<(EE + 255) / 256, 256>>>(ei);
    k_wsplit<<<(3 * KDIM * CC + 255) / 256, 256>>>(cw);
    k_xsplit<<<(HSZ + 255) / 256, 256>>>(x);

    for (int l = 0; l < 3; l++) {
        k_spmm<<<(NN + 7) / 8, 256>>>(x, l);
        dim3 grid((NN + 127) / 128, 2);
        k_gemm<<<grid, 256, SMEM_TOT>>>(bg, bb, l);
    }

    k_ranges<<<(NN + 255) / 256, 256>>>(batch);
    dim3 pg(GG, JKW / 128);
    k_pool<<<pg, 128>>>(out);
    k_cls<<<GG, 256>>>(out, w1, b1, cg, cbe, w2, b2, out);
}

// round 5
// speedup vs baseline: 2.0528x; 1.2613x over previous
#include <cuda_runtime.h>
#include <cuda_fp16.h>
#include <cstdint>

#define NN 20000
#define EE 320000
#define CC 256
#define GG 50
#define JKW 768
#define KDIM 512
#define HSZ (NN * CC)
#define NB 79                     // ceil(20000/256)

#define STG_BYTES 30720          // A big 10240 | A sml 10240 | B big 10240
#define SMEM_TOT (2 * STG_BYTES) // 60 KB, double buffered

// ---- scratch (static device globals; no runtime allocation) ----
__device__ int   g_degi[NN];
__device__ int   g_cnt[NN];
__device__ float g_dis[NN];
__device__ int   g_rowptr[NN + 1];
__device__ int   g_bsum[NB];
__device__ int   g_boff[NB];
__device__ int   g_ccol[EE];
__device__ float g_cw[EE];
__device__ __align__(16) float  g_jk[NN * JKW];     // [h0 | h1 | h2] fp32 (pool)
__device__ __align__(16) __half g_hb[2 * HSZ];      // h big,  ping-pong by layer
__device__ __align__(16) __half g_hs[2 * HSZ];      // h small (unscaled residual)
__device__ __align__(16) __half g_pb[HSZ];          // p big
__device__ __align__(16) __half g_ps[HSZ];          // p small
__device__ __align__(16) __half g_wb[3 * CC * KDIM];// W^T big  [l][n][k]
__device__ int   g_gstart[GG];
__device__ int   g_gend[GG];

// ---------------- helpers ----------------
__device__ __forceinline__ uint32_t smem_u32(const void* p) {
    uint32_t a;
    asm("{ .reg .u64 t; cvta.to.shared.u64 t, %1; cvt.u32.u64 %0, t; }" : "=r"(a) : "l"(p));
    return a;
}

__device__ __forceinline__ void cpa16(uint32_t dst, const void* src, int sz) {
    asm volatile("cp.async.ca.shared.global [%0], [%1], 16, %2;\n"
                 :: "r"(dst), "l"(src), "r"(sz));
}

__device__ __forceinline__ void mma_f16(float& d0, float& d1, float& d2, float& d3,
                                        uint32_t a0, uint32_t a1, uint32_t a2, uint32_t a3,
                                        uint32_t b0, uint32_t b1) {
    asm volatile(
        "mma.sync.aligned.m16n8k16.row.col.f32.f16.f16.f32 "
        "{%0,%1,%2,%3}, {%4,%5,%6,%7}, {%8,%9}, {%0,%1,%2,%3};"
        : "+f"(d0), "+f"(d1), "+f"(d2), "+f"(d3)
        : "r"(a0), "r"(a1), "r"(a2), "r"(a3), "r"(b0), "r"(b1));
}

__device__ __forceinline__ void split2(float v, __half& b, __half& s) {
    b = __float2half_rn(v);
    s = __float2half_rn(v - __half2float(b));
}

// ---------------------------------------------------------------
__global__ void k_zero() {
    int i = blockIdx.x * blockDim.x + threadIdx.x;
    if (i < NN) { g_degi[i] = 0; g_cnt[i] = 0; }
}

__global__ void k_deg(const int* __restrict__ ei) {
    int e = blockIdx.x * blockDim.x + threadIdx.x;
    if (e < EE) atomicAdd(&g_degi[ei[e]], 1);
}

// block sums of deg + dis computation (replaces k_dis + part of scan)
__global__ void k_bsum() {
    __shared__ int red[8];
    int i = blockIdx.x * 256 + threadIdx.x;
    int d = 0;
    if (i < NN) {
        d = g_degi[i];
        g_dis[i] = (d > 0) ? rsqrtf((float)d) : 0.0f;
    }
    int v = d;
#pragma unroll
    for (int off = 16; off; off >>= 1) v += __shfl_down_sync(0xffffffffu, v, off);
    if ((threadIdx.x & 31) == 0) red[threadIdx.x >> 5] = v;
    __syncthreads();
    if (threadIdx.x < 8) {
        int s = red[threadIdx.x];
#pragma unroll
        for (int off = 4; off; off >>= 1) s += __shfl_down_sync(0xffu, s, off);
        if (threadIdx.x == 0) g_bsum[blockIdx.x] = s;
    }
}

// single small block: exclusive scan of NB block sums
__global__ void k_scan2() {
    __shared__ int sm[128];
    int t = threadIdx.x;
    int v = (t < NB) ? g_bsum[t] : 0;
    sm[t] = v;
    __syncthreads();
#pragma unroll
    for (int off = 1; off < 128; off <<= 1) {
        int u = (t >= off) ? sm[t - off] : 0;
        __syncthreads();
        sm[t] += u;
        __syncthreads();
    }
    if (t < NB) g_boff[t] = sm[t] - v;
    if (t == NB - 1) g_rowptr[NN] = sm[t];
}

// per-block exclusive scan + base offset -> rowptr
__global__ void k_off() {
    __shared__ int sm[256];
    int t = threadIdx.x;
    int i = blockIdx.x * 256 + t;
    int v = (i < NN) ? g_degi[i] : 0;
    sm[t] = v;
    __syncthreads();
#pragma unroll
    for (int off = 1; off < 256; off <<= 1) {
        int u = (t >= off) ? sm[t - off] : 0;
        __syncthreads();
        sm[t] += u;
        __syncthreads();
    }
    if (i < NN) g_rowptr[i] = g_boff[blockIdx.x] + sm[t] - v;
}

__global__ void k_fill(const int* __restrict__ ei) {
    int e = blockIdx.x * blockDim.x + threadIdx.x;
    if (e < EE) {
        int r = ei[e];
        int c = ei[e + EE];
        int pos = g_rowptr[r] + atomicAdd(&g_cnt[r], 1);
        g_ccol[pos] = c;
        g_cw[pos]   = -(g_dis[r] * g_dis[c]);
    }
}

// ---------------------------------------------------------------
// fused prep: x split (vectorized 4/thread) + W big split + graph ranges
#define PREP_X (HSZ / 4)
#define PREP_W (3 * KDIM * CC)
__global__ void k_prep(const float* __restrict__ x, const float* __restrict__ cw,
                       const int* __restrict__ batch) {
    int i = blockIdx.x * 256 + threadIdx.x;
    if (i < PREP_X) {
        float4 v = *reinterpret_cast<const float4*>(x + (size_t)i * 4);
        __half b0, b1, b2, b3, s0, s1, s2, s3;
        split2(v.x, b0, s0); split2(v.y, b1, s1);
        split2(v.z, b2, s2); split2(v.w, b3, s3);
        __half2* hb = reinterpret_cast<__half2*>(g_hb + (size_t)i * 4);
        __half2* hs = reinterpret_cast<__half2*>(g_hs + (size_t)i * 4);
        hb[0] = __halves2half2(b0, b1); hb[1] = __halves2half2(b2, b3);
        hs[0] = __halves2half2(s0, s1); hs[1] = __halves2half2(s2, s3);
        return;
    }
    i -= PREP_X;
    if (i < PREP_W) {
        int n = i & 255;
        int k = (i >> 8) & 511;
        int l = i >> 17;
        g_wb[((size_t)l * CC + n) * KDIM + k] =
            __float2half_rn(cw[((size_t)l * KDIM + k) * CC + n]);
        return;
    }
    i -= PREP_W;
    if (i < NN) {
        int b = batch[i];
        if (i == 0 || batch[i - 1] != b) g_gstart[b] = i;
        if (i == NN - 1 || batch[i + 1] != b) g_gend[b] = i + 1;
    }
}

// ---------------------------------------------------------------
// SpMM (fp16 input): p[v,:] = sum_{CSR(v)} w * h16[col,:]; fp32 accum; split output.
__global__ void k_spmm(int layer) {
    int w = (blockIdx.x * blockDim.x + threadIdx.x) >> 5;
    int lane = threadIdx.x & 31;
    if (w >= NN) return;
    const __half* hin = g_hb + (size_t)(layer & 1) * HSZ;

    float acc[8];
#pragma unroll
    for (int q = 0; q < 8; q++) acc[q] = 0.f;

    int s = g_rowptr[w], e = g_rowptr[w + 1];
    for (int i = s; i < e; i++) {
        int u = g_ccol[i];
        float wt = g_cw[i];
        uint4 raw = __ldg(reinterpret_cast<const uint4*>(hin + (size_t)u * CC + lane * 8));
        const __half2* hp = reinterpret_cast<const __half2*>(&raw);
#pragma unroll
        for (int q = 0; q < 4; q++) {
            float2 f = __half22float2(hp[q]);
            acc[2 * q]     += wt * f.x;
            acc[2 * q + 1] += wt * f.y;
        }
    }
    __half bh[8], sh[8];
#pragma unroll
    for (int q = 0; q < 8; q++) split2(acc[q], bh[q], sh[q]);
    size_t o = (size_t)w * CC + lane * 8;
    __half2* pb = reinterpret_cast<__half2*>(g_pb + o);
    __half2* ps = reinterpret_cast<__half2*>(g_ps + o);
#pragma unroll
    for (int q = 0; q < 4; q++) {
        pb[q] = __halves2half2(bh[2 * q], bh[2 * q + 1]);
        ps[q] = __halves2half2(sh[2 * q], sh[2 * q + 1]);
    }
}

// ---------------------------------------------------------------
// Tile loader: A 128x32 (big+small) + B 128x32 (big), rows padded to 40 halves (80 B).
__device__ __forceinline__ void issue_tile(
    uint32_t sb, int stage, int kt, int m0, int n0,
    const __half* __restrict__ hb, const __half* __restrict__ hs,
    const __half* __restrict__ wb, int tid)
{
    uint32_t base = sb + stage * STG_BYTES;
    int kbase = kt * 32;
    const __half* ab; const __half* asml; int acol;
    if (kbase < CC) { ab = hb;   asml = hs;   acol = kbase; }
    else            { ab = g_pb; asml = g_ps; acol = kbase - CC; }
#pragma unroll
    for (int rep = 0; rep < 4; rep++) {
        int idx = tid + rep * 256;       // 0..1023
        int arr = idx >> 9;              // 0 big, 1 small
        int r   = (idx >> 2) & 127;
        int ch  = idx & 3;
        const __half* s0 = arr ? asml : ab;
        int gr = m0 + r;
        int sz = (gr < NN) ? 16 : 0;
        if (gr >= NN) gr = NN - 1;
        cpa16(base + arr * 10240 + r * 80 + ch * 16,
              s0 + (size_t)gr * CC + acol + ch * 8, sz);
    }
#pragma unroll
    for (int rep = 0; rep < 2; rep++) {
        int idx = tid + rep * 256;       // 0..511
        int r   = (idx >> 2) & 127;
        int ch  = idx & 3;
        cpa16(base + 20480 + r * 80 + ch * 16,
              wb + (size_t)(n0 + r) * KDIM + kbase + ch * 8, 16);
    }
}

// ---------------------------------------------------------------
// fp16x2 GEMM: g_jk[:, l*256+n0..] = BN/ReLU([h|p] @ W); writes next-layer h split.
__global__ __launch_bounds__(256, 2) void k_gemm(
    const float* __restrict__ gamma,
    const float* __restrict__ beta,
    int layer)
{
    extern __shared__ char smc[];
    uint32_t sb = smem_u32(smc);
    const int tid = threadIdx.x;
    const int wid = tid >> 5, lane = tid & 31;
    const int wm = wid >> 2, wn = wid & 3;
    const int gid = lane >> 2, tig = lane & 3;
    const int m0 = blockIdx.x * 128;
    const int n0 = blockIdx.y * 128;

    const __half* hb = g_hb + (size_t)(layer & 1) * HSZ;
    const __half* hs = g_hs + (size_t)(layer & 1) * HSZ;
    const __half* wb = g_wb + (size_t)layer * CC * KDIM;

    float acc[4][4][4];
#pragma unroll
    for (int mi = 0; mi < 4; mi++)
#pragma unroll
        for (int ni = 0; ni < 4; ni++)
#pragma unroll
            for (int r = 0; r < 4; r++) acc[mi][ni][r] = 0.f;

    issue_tile(sb, 0, 0, m0, n0, hb, hs, wb, tid);
    asm volatile("cp.async.commit_group;");

    for (int kt = 0; kt < 16; kt++) {
        if (kt < 15) {
            issue_tile(sb, (kt + 1) & 1, kt + 1, m0, n0, hb, hs, wb, tid);
            asm volatile("cp.async.commit_group;");
            asm volatile("cp.async.wait_group 1;");
        } else {
            asm volatile("cp.async.wait_group 0;");
        }
        __syncthreads();

        const int stg = (kt & 1) * STG_BYTES;
#pragma unroll
        for (int ks = 0; ks < 2; ks++) {
            const int kk = ks * 16;
            uint32_t bb[4][2];
#pragma unroll
            for (int ni = 0; ni < 4; ni++) {
                int boff = stg + 20480 + (wn * 32 + ni * 8 + gid) * 80 + (kk + 2 * tig) * 2;
                bb[ni][0] = *reinterpret_cast<const uint32_t*>(smc + boff);
                bb[ni][1] = *reinterpret_cast<const uint32_t*>(smc + boff + 16);
            }
#pragma unroll
            for (int mi = 0; mi < 4; mi++) {
                int aoff = stg + (wm * 64 + mi * 16 + gid) * 80 + (kk + 2 * tig) * 2;
                uint32_t ab0 = *reinterpret_cast<const uint32_t*>(smc + aoff);
                uint32_t ab1 = *reinterpret_cast<const uint32_t*>(smc + aoff + 640);
                uint32_t ab2 = *reinterpret_cast<const uint32_t*>(smc + aoff + 16);
                uint32_t ab3 = *reinterpret_cast<const uint32_t*>(smc + aoff + 656);
                uint32_t as0 = *reinterpret_cast<const uint32_t*>(smc + aoff + 10240);
                uint32_t as1 = *reinterpret_cast<const uint32_t*>(smc + aoff + 10240 + 640);
                uint32_t as2 = *reinterpret_cast<const uint32_t*>(smc + aoff + 10240 + 16);
                uint32_t as3 = *reinterpret_cast<const uint32_t*>(smc + aoff + 10240 + 656);
#pragma unroll
                for (int ni = 0; ni < 4; ni++) {
                    mma_f16(acc[mi][ni][0], acc[mi][ni][1], acc[mi][ni][2], acc[mi][ni][3],
                            ab0, ab1, ab2, ab3, bb[ni][0], bb[ni][1]);
                    mma_f16(acc[mi][ni][0], acc[mi][ni][1], acc[mi][ni][2], acc[mi][ni][3],
                            as0, as1, as2, as3, bb[ni][0], bb[ni][1]);
                }
            }
        }
        __syncthreads();
    }

    // epilogue: BN/ReLU, write g_jk fp32 + next-layer h split (layers 0,1)
    const float inv = rsqrtf(1.0f + 1e-5f);
    __half* ob = g_hb + (size_t)((layer + 1) & 1) * HSZ;
    __half* os = g_hs + (size_t)((layer + 1) & 1) * HSZ;
    const bool wr_split = (layer < 2);
#pragma unroll
    for (int ni = 0; ni < 4; ni++) {
        int c = n0 + wn * 32 + ni * 8 + 2 * tig;
        float s0 = __ldg(&gamma[layer * CC + c])     * inv;
        float s1 = __ldg(&gamma[layer * CC + c + 1]) * inv;
        float b0 = __ldg(&beta[layer * CC + c]);
        float b1 = __ldg(&beta[layer * CC + c + 1]);
#pragma unroll
        for (int mi = 0; mi < 4; mi++) {
            int r0 = m0 + wm * 64 + mi * 16 + gid;
            int r1 = r0 + 8;
            float v0 = acc[mi][ni][0], v1 = acc[mi][ni][1];
            float v2 = acc[mi][ni][2], v3 = acc[mi][ni][3];
            float o0, o1, o2, o3;
            if (layer == 0) {
                o0 = fmaxf(v0 * s0 + b0, 0.f); o1 = fmaxf(v1 * s1 + b1, 0.f);
                o2 = fmaxf(v2 * s0 + b0, 0.f); o3 = fmaxf(v3 * s1 + b1, 0.f);
            } else {
                o0 = fmaxf(v0, 0.f) * s0 + b0; o1 = fmaxf(v1, 0.f) * s1 + b1;
                o2 = fmaxf(v2, 0.f) * s0 + b0; o3 = fmaxf(v3, 0.f) * s1 + b1;
            }
            if (r0 < NN) {
                *reinterpret_cast<float2*>(&g_jk[(size_t)r0 * JKW + layer * CC + c]) = make_float2(o0, o1);
                if (wr_split) {
                    __half hb0, hs0, hb1, hs1;
                    split2(o0, hb0, hs0); split2(o1, hb1, hs1);
                    *reinterpret_cast<__half2*>(&ob[(size_t)r0 * CC + c]) = __halves2half2(hb0, hb1);
                    *reinterpret_cast<__half2*>(&os[(size_t)r0 * CC + c]) = __halves2half2(hs0, hs1);
                }
            }
            if (r1 < NN) {
                *reinterpret_cast<float2*>(&g_jk[(size_t)r1 * JKW + layer * CC + c]) = make_float2(o2, o3);
                if (wr_split) {
                    __half hb0, hs0, hb1, hs1;
                    split2(o2, hb0, hs0); split2(o3, hb1, hs1);
                    *reinterpret_cast<__half2*>(&ob[(size_t)r1 * CC + c]) = __halves2half2(hb0, hb1);
                    *reinterpret_cast<__half2*>(&os[(size_t)r1 * CC + c]) = __halves2half2(hs0, hs1);
                }
            }
        }
    }
}

// ---------------------------------------------------------------
__global__ void k_pool(float* __restrict__ out) {
    int g = blockIdx.x;
    int c = blockIdx.y * 128 + threadIdx.x;
    int s = g_gstart[g], e = g_gend[g];
    float acc = 0.f;
    for (int n = s; n < e; n++)
        acc += g_jk[(size_t)n * JKW + c];
    out[g * JKW + c] = acc / (float)(e - s);
}

__global__ void k_cls(const float* __restrict__ zin,
                      const float* __restrict__ W1, const float* __restrict__ b1,
                      const float* __restrict__ cg, const float* __restrict__ cbe,
                      const float* __restrict__ W2, const float* __restrict__ b2,
                      float* __restrict__ out)
{
    __shared__ float zr[JKW];
    __shared__ float zz[256];
    int g = blockIdx.x, t = threadIdx.x;
    for (int j = t; j < JKW; j += 256) zr[j] = zin[g * JKW + j];
    __syncthreads();

    float acc = b1[t];
    const float* w = W1 + (size_t)t * JKW;
    for (int j = 0; j < JKW; j++) acc += zr[j] * w[j];
    const float inv = rsqrtf(1.0f + 1e-5f);
    zz[t] = fmaxf(acc, 0.f) * cg[t] * inv + cbe[t];
    __syncthreads();

    if (t < 64) {
        int k = t >> 5;
        int lane = t & 31;
        float s = 0.f;
        for (int o = lane; o < 256; o += 32) s += zz[o] * W2[k * 256 + o];
#pragma unroll
        for (int off = 16; off; off >>= 1) s += __shfl_down_sync(0xffffffffu, s, off);
        if (lane == 0) out[GG * JKW + g * 2 + k] = s + b2[k];
    }
}

// ---------------------------------------------------------------
extern "C" void kernel_launch(void* const* d_in, const int* in_sizes, int n_in,
                              void* d_out, int out_size)
{
    const float* x    = (const float*)d_in[0];
    const int*   ei   = (const int*)  d_in[1];
    const int*   batch= (const int*)  d_in[2];
    const float* cw   = (const float*)d_in[3];
    const float* bg   = (const float*)d_in[4];
    const float* bb   = (const float*)d_in[5];
    const float* w1   = (const float*)d_in[6];
    const float* b1   = (const float*)d_in[7];
    const float* cg   = (const float*)d_in[8];
    const float* cbe  = (const float*)d_in[9];
    const float* w2   = (const float*)d_in[10];
    const float* b2   = (const float*)d_in[11];
    float* out = (float*)d_out;

    cudaFuncSetAttribute(k_gemm, cudaFuncAttributeMaxDynamicSharedMemorySize, SMEM_TOT);

    int prep_total = PREP_X + PREP_W + NN;
    k_prep<<<(prep_total + 255) / 256, 256>>>(x, cw, batch);
    k_zero<<<(NN + 255) / 256, 256>>>();
    k_deg <<<(EE + 255) / 256, 256>>>(ei);
    k_bsum<<<NB, 256>>>();
    k_scan2<<<1, 128>>>();
    k_off <<<NB, 256>>>();
    k_fill<<<(EE + 255) / 256, 256>>>(ei);

    for (int l = 0; l < 3; l++) {
        k_spmm<<<(NN + 7) / 8, 256>>>(l);
        dim3 grid((NN + 127) / 128, 2);
        k_gemm<<<grid, 256, SMEM_TOT>>>(bg, bb, l);
    }

    dim3 pg(GG, JKW / 128);
    k_pool<<<pg, 128>>>(out);
    k_cls<<<GG, 256>>>(out, w1, b1, cg, cbe, w2, b2, out);
}

// round 6
// speedup vs baseline: 2.3157x; 1.1281x over previous
#include <cuda_runtime.h>
#include <cuda_fp16.h>
#include <cstdint>

#define NN 20000
#define EE 320000
#define CC 256
#define GG 50
#define JKW 768
#define KDIM 512
#define HSZ (NN * CC)
#define NB 79                     // ceil(20000/256)
#define OUTSZ (GG * JKW + GG * 2) // 38500

#define STG_BYTES 30720          // A big 10240 | A sml 10240 | B big 10240
#define SMEM_TOT (2 * STG_BYTES) // 60 KB, double buffered

// ---- scratch (static device globals; no runtime allocation) ----
__device__ int   g_degi[NN];
__device__ int   g_cnt[NN];
__device__ float g_dis[NN];
__device__ int   g_rowptr[NN + 1];
__device__ int   g_bsum[NB];
__device__ int   g_boff[NB];
__device__ int   g_ccol[EE];
__device__ float g_cw[EE];
__device__ __align__(16) __half g_hb[2 * HSZ];      // h big,  ping-pong by layer
__device__ __align__(16) __half g_hs[2 * HSZ];      // h small (unscaled residual)
__device__ __align__(16) __half g_pb[HSZ];          // p big
__device__ __align__(16) __half g_ps[HSZ];          // p small
__device__ __align__(16) __half g_wb[3 * CC * KDIM];// W^T big  [l][n][k]
__device__ int   g_gstart[GG];
__device__ int   g_gend[GG];

// ---------------- helpers ----------------
__device__ __forceinline__ uint32_t smem_u32(const void* p) {
    uint32_t a;
    asm("{ .reg .u64 t; cvta.to.shared.u64 t, %1; cvt.u32.u64 %0, t; }" : "=r"(a) : "l"(p));
    return a;
}

__device__ __forceinline__ void cpa16(uint32_t dst, const void* src, int sz) {
    asm volatile("cp.async.ca.shared.global [%0], [%1], 16, %2;\n"
                 :: "r"(dst), "l"(src), "r"(sz));
}

__device__ __forceinline__ void mma_f16(float& d0, float& d1, float& d2, float& d3,
                                        uint32_t a0, uint32_t a1, uint32_t a2, uint32_t a3,
                                        uint32_t b0, uint32_t b1) {
    asm volatile(
        "mma.sync.aligned.m16n8k16.row.col.f32.f16.f16.f32 "
        "{%0,%1,%2,%3}, {%4,%5,%6,%7}, {%8,%9}, {%0,%1,%2,%3};"
        : "+f"(d0), "+f"(d1), "+f"(d2), "+f"(d3)
        : "r"(a0), "r"(a1), "r"(a2), "r"(a3), "r"(b0), "r"(b1));
}

__device__ __forceinline__ void ldmx4(uint32_t& r0, uint32_t& r1, uint32_t& r2, uint32_t& r3,
                                      uint32_t addr) {
    asm volatile("ldmatrix.sync.aligned.m8n8.x4.shared.b16 {%0,%1,%2,%3}, [%4];"
                 : "=r"(r0), "=r"(r1), "=r"(r2), "=r"(r3) : "r"(addr));
}

__device__ __forceinline__ void split2(float v, __half& b, __half& s) {
    b = __float2half_rn(v);
    s = __float2half_rn(v - __half2float(b));
}

// ---------------------------------------------------------------
__global__ void k_deg(const int* __restrict__ ei) {
    int e = blockIdx.x * blockDim.x + threadIdx.x;
    if (e < EE) atomicAdd(&g_degi[ei[e]], 1);
}

// block sums of deg + dis computation
__global__ void k_bsum() {
    __shared__ int red[8];
    int i = blockIdx.x * 256 + threadIdx.x;
    int d = 0;
    if (i < NN) {
        d = g_degi[i];
        g_dis[i] = (d > 0) ? rsqrtf((float)d) : 0.0f;
    }
    int v = d;
#pragma unroll
    for (int off = 16; off; off >>= 1) v += __shfl_down_sync(0xffffffffu, v, off);
    if ((threadIdx.x & 31) == 0) red[threadIdx.x >> 5] = v;
    __syncthreads();
    if (threadIdx.x < 8) {
        int s = red[threadIdx.x];
#pragma unroll
        for (int off = 4; off; off >>= 1) s += __shfl_down_sync(0xffu, s, off);
        if (threadIdx.x == 0) g_bsum[blockIdx.x] = s;
    }
}

__global__ void k_scan2() {
    __shared__ int sm[128];
    int t = threadIdx.x;
    int v = (t < NB) ? g_bsum[t] : 0;
    sm[t] = v;
    __syncthreads();
#pragma unroll
    for (int off = 1; off < 128; off <<= 1) {
        int u = (t >= off) ? sm[t - off] : 0;
        __syncthreads();
        sm[t] += u;
        __syncthreads();
    }
    if (t < NB) g_boff[t] = sm[t] - v;
    if (t == NB - 1) g_rowptr[NN] = sm[t];
}

__global__ void k_off() {
    __shared__ int sm[256];
    int t = threadIdx.x;
    int i = blockIdx.x * 256 + t;
    int v = (i < NN) ? g_degi[i] : 0;
    sm[t] = v;
    __syncthreads();
#pragma unroll
    for (int off = 1; off < 256; off <<= 1) {
        int u = (t >= off) ? sm[t - off] : 0;
        __syncthreads();
        sm[t] += u;
        __syncthreads();
    }
    if (i < NN) g_rowptr[i] = g_boff[blockIdx.x] + sm[t] - v;
}

__global__ void k_fill(const int* __restrict__ ei) {
    int e = blockIdx.x * blockDim.x + threadIdx.x;
    if (e < EE) {
        int r = ei[e];
        int c = ei[e + EE];
        int pos = g_rowptr[r] + atomicAdd(&g_cnt[r], 1);
        g_ccol[pos] = c;
        g_cw[pos]   = -(g_dis[r] * g_dis[c]);
    }
}

// ---------------------------------------------------------------
// fused prep: x split + W big + deg/cnt zero + graph ranges + out zero
#define PREP_X (HSZ / 4)
#define PREP_W (3 * KDIM * CC)
__global__ void k_prep(const float* __restrict__ x, const float* __restrict__ cw,
                       const int* __restrict__ batch, float* __restrict__ out) {
    int i = blockIdx.x * 256 + threadIdx.x;
    if (i < PREP_X) {
        float4 v = *reinterpret_cast<const float4*>(x + (size_t)i * 4);
        __half b0, b1, b2, b3, s0, s1, s2, s3;
        split2(v.x, b0, s0); split2(v.y, b1, s1);
        split2(v.z, b2, s2); split2(v.w, b3, s3);
        __half2* hb = reinterpret_cast<__half2*>(g_hb + (size_t)i * 4);
        __half2* hs = reinterpret_cast<__half2*>(g_hs + (size_t)i * 4);
        hb[0] = __halves2half2(b0, b1); hb[1] = __halves2half2(b2, b3);
        hs[0] = __halves2half2(s0, s1); hs[1] = __halves2half2(s2, s3);
        return;
    }
    i -= PREP_X;
    if (i < PREP_W) {
        int n = i & 255;
        int k = (i >> 8) & 511;
        int l = i >> 17;
        g_wb[((size_t)l * CC + n) * KDIM + k] =
            __float2half_rn(cw[((size_t)l * KDIM + k) * CC + n]);
        return;
    }
    i -= PREP_W;
    if (i < NN) {
        g_degi[i] = 0;
        g_cnt[i] = 0;
        int b = batch[i];
        if (i == 0 || batch[i - 1] != b) g_gstart[b] = i;
        if (i == NN - 1 || batch[i + 1] != b) g_gend[b] = i + 1;
        return;
    }
    i -= NN;
    if (i < OUTSZ) out[i] = 0.0f;
}

// ---------------------------------------------------------------
// SpMM (fp16 input): p[v,:] = sum_{CSR(v)} w * h16[col,:]; fp32 accum; split output.
__global__ void k_spmm(int layer) {
    int w = (blockIdx.x * blockDim.x + threadIdx.x) >> 5;
    int lane = threadIdx.x & 31;
    if (w >= NN) return;
    const __half* hin = g_hb + (size_t)(layer & 1) * HSZ;

    float acc[8];
#pragma unroll
    for (int q = 0; q < 8; q++) acc[q] = 0.f;

    int s = g_rowptr[w], e = g_rowptr[w + 1];
    for (int i = s; i < e; i++) {
        int u = g_ccol[i];
        float wt = g_cw[i];
        uint4 raw = __ldg(reinterpret_cast<const uint4*>(hin + (size_t)u * CC + lane * 8));
        const __half2* hp = reinterpret_cast<const __half2*>(&raw);
#pragma unroll
        for (int q = 0; q < 4; q++) {
            float2 f = __half22float2(hp[q]);
            acc[2 * q]     += wt * f.x;
            acc[2 * q + 1] += wt * f.y;
        }
    }
    __half bh[8], sh[8];
#pragma unroll
    for (int q = 0; q < 8; q++) split2(acc[q], bh[q], sh[q]);
    size_t o = (size_t)w * CC + lane * 8;
    __half2* pb = reinterpret_cast<__half2*>(g_pb + o);
    __half2* ps = reinterpret_cast<__half2*>(g_ps + o);
#pragma unroll
    for (int q = 0; q < 4; q++) {
        pb[q] = __halves2half2(bh[2 * q], bh[2 * q + 1]);
        ps[q] = __halves2half2(sh[2 * q], sh[2 * q + 1]);
    }
}

// ---------------------------------------------------------------
// Tile loader: A 128x32 (big+small) + B 128x32 (big), rows padded to 40 halves (80 B).
__device__ __forceinline__ void issue_tile(
    uint32_t sb, int stage, int kt, int m0, int n0,
    const __half* __restrict__ hb, const __half* __restrict__ hs,
    const __half* __restrict__ wb, int tid)
{
    uint32_t base = sb + stage * STG_BYTES;
    int kbase = kt * 32;
    const __half* ab; const __half* asml; int acol;
    if (kbase < CC) { ab = hb;   asml = hs;   acol = kbase; }
    else            { ab = g_pb; asml = g_ps; acol = kbase - CC; }
#pragma unroll
    for (int rep = 0; rep < 4; rep++) {
        int idx = tid + rep * 256;       // 0..1023
        int arr = idx >> 9;              // 0 big, 1 small
        int r   = (idx >> 2) & 127;
        int ch  = idx & 3;
        const __half* s0 = arr ? asml : ab;
        int gr = m0 + r;
        int sz = (gr < NN) ? 16 : 0;
        if (gr >= NN) gr = NN - 1;
        cpa16(base + arr * 10240 + r * 80 + ch * 16,
              s0 + (size_t)gr * CC + acol + ch * 8, sz);
    }
#pragma unroll
    for (int rep = 0; rep < 2; rep++) {
        int idx = tid + rep * 256;       // 0..511
        int r   = (idx >> 2) & 127;
        int ch  = idx & 3;
        cpa16(base + 20480 + r * 80 + ch * 16,
              wb + (size_t)(n0 + r) * KDIM + kbase + ch * 8, 16);
    }
}

// ---------------------------------------------------------------
// fp16x2 GEMM with fused BN/ReLU + next-layer split + fused graph-mean-pool.
__global__ __launch_bounds__(256, 2) void k_gemm(
    const float* __restrict__ gamma,
    const float* __restrict__ beta,
    float* __restrict__ out,
    int layer)
{
    extern __shared__ char smc[];
    uint32_t sb = smem_u32(smc);
    const int tid = threadIdx.x;
    const int wid = tid >> 5, lane = tid & 31;
    const int wm = wid >> 2, wn = wid & 3;
    const int gid = lane >> 2, tig = lane & 3;
    const int lrow = lane & 7, grp = lane >> 3;
    const int m0 = blockIdx.x * 128;
    const int n0 = blockIdx.y * 128;

    const __half* hb = g_hb + (size_t)(layer & 1) * HSZ;
    const __half* hs = g_hs + (size_t)(layer & 1) * HSZ;
    const __half* wb = g_wb + (size_t)layer * CC * KDIM;

    float acc[4][4][4];
#pragma unroll
    for (int mi = 0; mi < 4; mi++)
#pragma unroll
        for (int ni = 0; ni < 4; ni++)
#pragma unroll
            for (int r = 0; r < 4; r++) acc[mi][ni][r] = 0.f;

    // ldmatrix lane-address components (row parts independent of kk/stage)
    const uint32_t a_row = (uint32_t)(wm * 64 + ((grp & 1) << 3) + lrow) * 80;
    const uint32_t a_kof = (uint32_t)((grp >> 1) << 3) * 2;
    const uint32_t b_row = (uint32_t)(wn * 32 + ((grp >> 1) << 3) + lrow) * 80;
    const uint32_t b_kof = (uint32_t)((grp & 1) << 3) * 2;

    issue_tile(sb, 0, 0, m0, n0, hb, hs, wb, tid);
    asm volatile("cp.async.commit_group;");

    for (int kt = 0; kt < 16; kt++) {
        if (kt < 15) {
            issue_tile(sb, (kt + 1) & 1, kt + 1, m0, n0, hb, hs, wb, tid);
            asm volatile("cp.async.commit_group;");
            asm volatile("cp.async.wait_group 1;");
        } else {
            asm volatile("cp.async.wait_group 0;");
        }
        __syncthreads();

        const uint32_t stg = sb + (kt & 1) * STG_BYTES;
#pragma unroll
        for (int ks = 0; ks < 2; ks++) {
            const uint32_t kk2 = (uint32_t)(ks * 16) * 2;
            uint32_t bb[4][2];
#pragma unroll
            for (int np = 0; np < 2; np++) {
                uint32_t baddr = stg + 20480 + np * 16 * 80 + b_row + kk2 + b_kof;
                ldmx4(bb[2 * np][0], bb[2 * np][1], bb[2 * np + 1][0], bb[2 * np + 1][1], baddr);
            }
#pragma unroll
            for (int mi = 0; mi < 4; mi++) {
                uint32_t aaddr = stg + mi * 16 * 80 + a_row + kk2 + a_kof;
                uint32_t ab0, ab1, ab2, ab3, as0, as1, as2, as3;
                ldmx4(ab0, ab1, ab2, ab3, aaddr);
                ldmx4(as0, as1, as2, as3, aaddr + 10240);
#pragma unroll
                for (int ni = 0; ni < 4; ni++) {
                    mma_f16(acc[mi][ni][0], acc[mi][ni][1], acc[mi][ni][2], acc[mi][ni][3],
                            ab0, ab1, ab2, ab3, bb[ni][0], bb[ni][1]);
                    mma_f16(acc[mi][ni][0], acc[mi][ni][1], acc[mi][ni][2], acc[mi][ni][3],
                            as0, as1, as2, as3, bb[ni][0], bb[ni][1]);
                }
            }
        }
        __syncthreads();
    }

    // epilogue: BN/ReLU -> (a) next-layer h split (layers 0,1), (b) fused pool sums.
    const float inv = rsqrtf(1.0f + 1e-5f);
    __half* ob = g_hb + (size_t)((layer + 1) & 1) * HSZ;
    __half* os = g_hs + (size_t)((layer + 1) & 1) * HSZ;
    const bool wr_split = (layer < 2);
    const int gbase = m0 / 400;
#pragma unroll
    for (int ni = 0; ni < 4; ni++) {
        int c = n0 + wn * 32 + ni * 8 + 2 * tig;
        float s0 = __ldg(&gamma[layer * CC + c])     * inv;
        float s1 = __ldg(&gamma[layer * CC + c + 1]) * inv;
        float b0 = __ldg(&beta[layer * CC + c]);
        float b1 = __ldg(&beta[layer * CC + c + 1]);
        float ps[2][2] = {{0.f, 0.f}, {0.f, 0.f}};
#pragma unroll
        for (int mi = 0; mi < 4; mi++) {
            int r0 = m0 + wm * 64 + mi * 16 + gid;
            int r1 = r0 + 8;
            float v0 = acc[mi][ni][0], v1 = acc[mi][ni][1];
            float v2 = acc[mi][ni][2], v3 = acc[mi][ni][3];
            float o0, o1, o2, o3;
            if (layer == 0) {
                o0 = fmaxf(v0 * s0 + b0, 0.f); o1 = fmaxf(v1 * s1 + b1, 0.f);
                o2 = fmaxf(v2 * s0 + b0, 0.f); o3 = fmaxf(v3 * s1 + b1, 0.f);
            } else {
                o0 = fmaxf(v0, 0.f) * s0 + b0; o1 = fmaxf(v1, 0.f) * s1 + b1;
                o2 = fmaxf(v2, 0.f) * s0 + b0; o3 = fmaxf(v3, 0.f) * s1 + b1;
            }
            if (r0 < NN) {
                int sg = r0 / 400 - gbase;
                ps[sg][0] += o0; ps[sg][1] += o1;
                if (wr_split) {
                    __half hb0, hs0, hb1, hs1;
                    split2(o0, hb0, hs0); split2(o1, hb1, hs1);
                    *reinterpret_cast<__half2*>(&ob[(size_t)r0 * CC + c]) = __halves2half2(hb0, hb1);
                    *reinterpret_cast<__half2*>(&os[(size_t)r0 * CC + c]) = __halves2half2(hs0, hs1);
                }
            }
            if (r1 < NN) {
                int sg = r1 / 400 - gbase;
                ps[sg][0] += o2; ps[sg][1] += o3;
                if (wr_split) {
                    __half hb0, hs0, hb1, hs1;
                    split2(o2, hb0, hs0); split2(o3, hb1, hs1);
                    *reinterpret_cast<__half2*>(&ob[(size_t)r1 * CC + c]) = __halves2half2(hb0, hb1);
                    *reinterpret_cast<__half2*>(&os[(size_t)r1 * CC + c]) = __halves2half2(hs0, hs1);
                }
            }
        }
        // reduce across gid lanes (stride-4) and accumulate to out
#pragma unroll
        for (int sg = 0; sg < 2; sg++) {
#pragma unroll
            for (int cp = 0; cp < 2; cp++) {
                float v = ps[sg][cp];
                v += __shfl_down_sync(0xffffffffu, v, 16);
                v += __shfl_down_sync(0xffffffffu, v, 8);
                v += __shfl_down_sync(0xffffffffu, v, 4);
                if (lane < 4) {
                    int g = gbase + sg;
                    if (g < GG)
                        atomicAdd(&out[(size_t)g * JKW + layer * CC + c + cp], v);
                }
            }
        }
    }
}

// ---------------------------------------------------------------
// classifier: divide pool sums -> write mean to out -> Linear/ReLU/BN/Linear
__global__ void k_cls(const float* __restrict__ W1, const float* __restrict__ b1,
                      const float* __restrict__ cg, const float* __restrict__ cbe,
                      const float* __restrict__ W2, const float* __restrict__ b2,
                      float* __restrict__ out)
{
    __shared__ float zr[JKW];
    __shared__ float zz[256];
    int g = blockIdx.x, t = threadIdx.x;
    float rc = 1.0f / (float)(g_gend[g] - g_gstart[g]);
    for (int j = t; j < JKW; j += 256) {
        float v = out[(size_t)g * JKW + j] * rc;
        zr[j] = v;
        out[(size_t)g * JKW + j] = v;
    }
    __syncthreads();

    float acc = b1[t];
    const float* w = W1 + (size_t)t * JKW;
    for (int j = 0; j < JKW; j++) acc += zr[j] * w[j];
    const float inv = rsqrtf(1.0f + 1e-5f);
    zz[t] = fmaxf(acc, 0.f) * cg[t] * inv + cbe[t];
    __syncthreads();

    if (t < 64) {
        int k = t >> 5;
        int lane = t & 31;
        float s = 0.f;
        for (int o = lane; o < 256; o += 32) s += zz[o] * W2[k * 256 + o];
#pragma unroll
        for (int off = 16; off; off >>= 1) s += __shfl_down_sync(0xffffffffu, s, off);
        if (lane == 0) out[GG * JKW + g * 2 + k] = s + b2[k];
    }
}

// ---------------------------------------------------------------
extern "C" void kernel_launch(void* const* d_in, const int* in_sizes, int n_in,
                              void* d_out, int out_size)
{
    const float* x    = (const float*)d_in[0];
    const int*   ei   = (const int*)  d_in[1];
    const int*   batch= (const int*)  d_in[2];
    const float* cw   = (const float*)d_in[3];
    const float* bg   = (const float*)d_in[4];
    const float* bb   = (const float*)d_in[5];
    const float* w1   = (const float*)d_in[6];
    const float* b1   = (const float*)d_in[7];
    const float* cg   = (const float*)d_in[8];
    const float* cbe  = (const float*)d_in[9];
    const float* w2   = (const float*)d_in[10];
    const float* b2   = (const float*)d_in[11];
    float* out = (float*)d_out;

    cudaFuncSetAttribute(k_gemm, cudaFuncAttributeMaxDynamicSharedMemorySize, SMEM_TOT);

    int prep_total = PREP_X + PREP_W + NN + OUTSZ;
    k_prep<<<(prep_total + 255) / 256, 256>>>(x, cw, batch, out);
    k_deg <<<(EE + 255) / 256, 256>>>(ei);
    k_bsum<<<NB, 256>>>();
    k_scan2<<<1, 128>>>();
    k_off <<<NB, 256>>>();
    k_fill<<<(EE + 255) / 256, 256>>>(ei);

    for (int l = 0; l < 3; l++) {
        k_spmm<<<(NN + 7) / 8, 256>>>(l);
        dim3 grid((NN + 127) / 128, 2);
        k_gemm<<<grid, 256, SMEM_TOT>>>(bg, bb, out, l);
    }

    k_cls<<<GG, 256>>>(w1, b1, cg, cbe, w2, b2, out);
}